// round 8
// baseline (speedup 1.0000x reference)
#include <cuda_runtime.h>
#include <cuda_bf16.h>

// PyramidROIAlign R8: 128-thread blocks (16 CTAs/SM -> more independent
// streams, finer granularity, cheaper barriers). Two 64-lane float4 groups
// per block; cells strided by 2 with software-pipelined param prefetch.

#define POOL_W 7
#define NCELLS 49
#define NCH    256
#define NBOXES 1000
#define NBATCH 2

struct __align__(16) CellParam {
    int   o00, o01, o10, o11;   // corner byte offsets (channel 0)
    float a00, a01, a10, a11;   // bilinear weights * validity
};

__global__ __launch_bounds__(128, 16) void pyramid_roi_align_kernel(
    const float* __restrict__ boxes,
    const float* __restrict__ p3,      // [B,128,128,C]
    const float* __restrict__ p4,      // [B,64,64,C]
    const float* __restrict__ p5,      // [B,32,32,C]
    float* __restrict__ out)           // [B*N, 7, 7, C]
{
    __shared__ CellParam cp[NCELLS];

    const int box   = blockIdx.x;
    const int tid   = threadIdx.x;
    const int local = tid >> 6;        // group 0..1
    const int lane  = tid & 63;        // float4 channel group
    const int b     = (box >= NBOXES) ? 1 : 0;

    // ---- box scalars (broadcast loads; all threads) ----
    const float y1 = __ldg(boxes + box * 4 + 0);
    const float x1 = __ldg(boxes + box * 4 + 1);
    const float y2 = __ldg(boxes + box * 4 + 2);
    const float x2 = __ldg(boxes + box * 4 + 3);
    const float h  = y2 - y1;
    const float w  = x2 - x1;

    float lvlf = ceilf(5.0f + logf(h * w) / 0.6931471805599453f);
    lvlf = fminf(fmaxf(lvlf, 3.0f), 5.0f);
    const int level = (int)lvlf;

    const float* feat;
    int HW;
    if (level == 3)      { feat = p3; HW = 128; }
    else if (level == 4) { feat = p4; HW = 64;  }
    else                 { feat = p5; HW = 32;  }

    // ---- phase 1: per-cell params (threads 0..48); exact reference rounding
    //      for the discrete decisions (floor, clamp, validity) ----
    if (tid < NCELLS) {
        const float Hm1 = (float)(HW - 1);
        const int   iy  = tid / POOL_W;
        const int   ix  = tid - iy * POOL_W;
        const float stepy = __fdiv_rn(__fmul_rn(h, Hm1), 6.0f);
        const float stepx = __fdiv_rn(__fmul_rn(w, Hm1), 6.0f);
        const float ys = __fadd_rn(__fmul_rn(y1, Hm1), __fmul_rn((float)iy, stepy));
        const float xs = __fadd_rn(__fmul_rn(x1, Hm1), __fmul_rn((float)ix, stepx));

        const bool valid = (ys >= 0.0f) & (ys <= Hm1) & (xs >= 0.0f) & (xs <= Hm1);
        const float vm = valid ? 1.0f : 0.0f;

        const float y0f = floorf(ys);
        const float x0f = floorf(xs);
        const float wy  = ys - y0f;
        const float wx  = xs - x0f;
        const float owy = 1.0f - wy;
        const float owx = 1.0f - wx;

        const int y0i = (int)fminf(fmaxf(y0f, 0.0f), Hm1);
        const int y1i = (int)fminf(fmaxf(y0f + 1.0f, 0.0f), Hm1);
        const int x0i = (int)fminf(fmaxf(x0f, 0.0f), Hm1);
        const int x1i = (int)fminf(fmaxf(x0f + 1.0f, 0.0f), Hm1);

        const int rowbytes = HW * NCH * 4;
        CellParam p;
        p.o00 = y0i * rowbytes + x0i * (NCH * 4);
        p.o01 = y0i * rowbytes + x1i * (NCH * 4);
        p.o10 = y1i * rowbytes + x0i * (NCH * 4);
        p.o11 = y1i * rowbytes + x1i * (NCH * 4);
        p.a00 = owx * owy * vm;
        p.a01 = wx  * owy * vm;
        p.a10 = owx * wy  * vm;
        p.a11 = wx  * wy  * vm;
        cp[tid] = p;
    }
    __syncthreads();

    // ---- phase 2: stream channels; software-pipelined param prefetch ----
    const char* basep = (const char*)(feat + (size_t)b * HW * HW * NCH) + lane * 16;
    float4* outp = (float4*)out + (size_t)box * NCELLS * (NCH / 4) + lane;

    int4   oo = ((const int4*)&cp[local])[0];
    float4 aa = ((const float4*)&cp[local])[1];

    #pragma unroll 1
    for (int c = local; c < NCELLS; c += 2) {
        // issue current cell's loads immediately (addresses already known)
        const float4 v00 = __ldg((const float4*)(basep + oo.x));
        const float4 v01 = __ldg((const float4*)(basep + oo.y));
        const float4 v10 = __ldg((const float4*)(basep + oo.z));
        const float4 v11 = __ldg((const float4*)(basep + oo.w));

        // prefetch next cell's params while loads are in flight
        const int cn = c + 2;
        int4   oon;
        float4 aan;
        if (cn < NCELLS) {
            oon = ((const int4*)&cp[cn])[0];
            aan = ((const float4*)&cp[cn])[1];
        } else {
            oon = oo; aan = aa;
        }

        float4 o;
        o.x = v00.x * aa.x + v01.x * aa.y + v10.x * aa.z + v11.x * aa.w;
        o.y = v00.y * aa.x + v01.y * aa.y + v10.y * aa.z + v11.y * aa.w;
        o.z = v00.z * aa.x + v01.z * aa.y + v10.z * aa.z + v11.z * aa.w;
        o.w = v00.w * aa.x + v01.w * aa.y + v10.w * aa.z + v11.w * aa.w;

        __stcs(outp + (size_t)c * (NCH / 4), o);

        oo = oon;
        aa = aan;
    }
}

extern "C" void kernel_launch(void* const* d_in, const int* in_sizes, int n_in,
                              void* d_out, int out_size) {
    const float* boxes = (const float*)d_in[0];
    const float* p3    = (const float*)d_in[2];
    const float* p4    = (const float*)d_in[3];
    const float* p5    = (const float*)d_in[4];
    float* out = (float*)d_out;

    pyramid_roi_align_kernel<<<NBATCH * NBOXES, 128>>>(boxes, p3, p4, p5, out);
}

// round 9
// speedup vs baseline: 1.0009x; 1.0009x over previous
#include <cuda_runtime.h>
#include <cuda_bf16.h>

// PyramidROIAlign R9: two-kernel split.
// Kernel A: one thread per (box,cell) computes CellParam into __device__ scratch
//           (exact reference rounding for floor/clamp/validity).
//           (level,batch) selector packed into low bits of o00 (offsets are 1KB-multiples).
// Kernel B: pure gather, no smem/sync: 4 cells per 256-thread block, 64 float4-lanes
//           per cell. 2 broadcast LDG (params) + 4 LDG.128 + 16 FFMA + 1 STG.128.

#define POOL_W 7
#define NCELLS 49
#define NCH    256
#define NBOXES 1000
#define NBATCH 2
#define NTASKS (NBATCH * NBOXES * NCELLS)   // 98000

struct __align__(16) CellParam {
    int   o00, o01, o10, o11;   // corner byte offsets (channel 0); o00 low bits = sel
    float a00, a01, a10, a11;   // bilinear weights * validity
};

__device__ CellParam g_cp[NTASKS];

__global__ __launch_bounds__(256) void prep_kernel(const float* __restrict__ boxes)
{
    const int id = blockIdx.x * 256 + threadIdx.x;
    if (id >= NTASKS) return;

    const int box  = id / NCELLS;
    const int cell = id - box * NCELLS;
    const int b    = (box >= NBOXES) ? 1 : 0;

    const float y1 = __ldg(boxes + box * 4 + 0);
    const float x1 = __ldg(boxes + box * 4 + 1);
    const float y2 = __ldg(boxes + box * 4 + 2);
    const float x2 = __ldg(boxes + box * 4 + 3);
    const float h  = y2 - y1;
    const float w  = x2 - x1;

    float lvlf = ceilf(5.0f + logf(h * w) / 0.6931471805599453f);
    lvlf = fminf(fmaxf(lvlf, 3.0f), 5.0f);
    const int level = (int)lvlf;

    const int HW = (level == 3) ? 128 : (level == 4) ? 64 : 32;

    const float Hm1 = (float)(HW - 1);
    const int   iy  = cell / POOL_W;
    const int   ix  = cell - iy * POOL_W;
    // exact reference rounding order
    const float stepy = __fdiv_rn(__fmul_rn(h, Hm1), 6.0f);
    const float stepx = __fdiv_rn(__fmul_rn(w, Hm1), 6.0f);
    const float ys = __fadd_rn(__fmul_rn(y1, Hm1), __fmul_rn((float)iy, stepy));
    const float xs = __fadd_rn(__fmul_rn(x1, Hm1), __fmul_rn((float)ix, stepx));

    const bool  valid = (ys >= 0.0f) & (ys <= Hm1) & (xs >= 0.0f) & (xs <= Hm1);
    const float vm = valid ? 1.0f : 0.0f;

    const float y0f = floorf(ys);
    const float x0f = floorf(xs);
    const float wy  = ys - y0f;
    const float wx  = xs - x0f;
    const float owy = 1.0f - wy;
    const float owx = 1.0f - wx;

    const int y0i = (int)fminf(fmaxf(y0f, 0.0f), Hm1);
    const int y1i = (int)fminf(fmaxf(y0f + 1.0f, 0.0f), Hm1);
    const int x0i = (int)fminf(fmaxf(x0f, 0.0f), Hm1);
    const int x1i = (int)fminf(fmaxf(x0f + 1.0f, 0.0f), Hm1);

    const int rowbytes = HW * NCH * 4;
    const int sel = (level - 3) * 2 + b;        // 0..5, fits in low bits

    CellParam p;
    p.o00 = (y0i * rowbytes + x0i * (NCH * 4)) | sel;
    p.o01 = y0i * rowbytes + x1i * (NCH * 4);
    p.o10 = y1i * rowbytes + x0i * (NCH * 4);
    p.o11 = y1i * rowbytes + x1i * (NCH * 4);
    p.a00 = owx * owy * vm;
    p.a01 = wx  * owy * vm;
    p.a10 = owx * wy  * vm;
    p.a11 = wx  * wy  * vm;
    g_cp[id] = p;
}

__global__ __launch_bounds__(256) void gather_kernel(
    const float* __restrict__ p3,
    const float* __restrict__ p4,
    const float* __restrict__ p5,
    float* __restrict__ out)
{
    const int pt   = blockIdx.x * 4 + (threadIdx.x >> 6);   // NTASKS % 4 == 0
    const int lane = threadIdx.x & 63;

    int4   oo = ((const int4*)&g_cp[pt])[0];
    float4 aa = ((const float4*)&g_cp[pt])[1];

    const int sel = oo.x & 7;
    oo.x &= ~1023;                      // offsets are multiples of 1024

    const int lvl = sel >> 1;
    const int b   = sel & 1;
    const float* fb;
    int HW;
    if (lvl == 0)      { fb = p3; HW = 128; }
    else if (lvl == 1) { fb = p4; HW = 64;  }
    else               { fb = p5; HW = 32;  }

    const char* basep = (const char*)(fb + (size_t)b * HW * HW * NCH) + lane * 16;

    const float4 v00 = __ldg((const float4*)(basep + oo.x));
    const float4 v01 = __ldg((const float4*)(basep + oo.y));
    const float4 v10 = __ldg((const float4*)(basep + oo.z));
    const float4 v11 = __ldg((const float4*)(basep + oo.w));

    float4 o;
    o.x = v00.x * aa.x + v01.x * aa.y + v10.x * aa.z + v11.x * aa.w;
    o.y = v00.y * aa.x + v01.y * aa.y + v10.y * aa.z + v11.y * aa.w;
    o.z = v00.z * aa.x + v01.z * aa.y + v10.z * aa.z + v11.z * aa.w;
    o.w = v00.w * aa.x + v01.w * aa.y + v10.w * aa.z + v11.w * aa.w;

    __stcs((float4*)out + (size_t)pt * 64 + lane, o);
}

extern "C" void kernel_launch(void* const* d_in, const int* in_sizes, int n_in,
                              void* d_out, int out_size) {
    const float* boxes = (const float*)d_in[0];
    const float* p3    = (const float*)d_in[2];
    const float* p4    = (const float*)d_in[3];
    const float* p5    = (const float*)d_in[4];
    float* out = (float*)d_out;

    prep_kernel<<<(NTASKS + 255) / 256, 256>>>(boxes);
    gather_kernel<<<NTASKS / 4, 256>>>(p3, p4, p5, out);
}

// round 10
// speedup vs baseline: 1.1145x; 1.1135x over previous
#include <cuda_runtime.h>
#include <cuda_bf16.h>

// PyramidROIAlign R10: prep kernel (per-cell params -> __device__ scratch) +
// looped gather: 256-thread blocks, 4 groups x 64 float4-lanes, each group
// handles 4 consecutive cells. No smem, no syncthreads, fine-grained blocks
// (6125) to eliminate wave-tail, 4-iteration loop to amortize cold-start.

#define POOL_W 7
#define NCELLS 49
#define NCH    256
#define NBOXES 1000
#define NBATCH 2
#define NTASKS (NBATCH * NBOXES * NCELLS)   // 98000
#define CELLS_PER_GROUP 4
#define TASKS_PER_BLOCK (4 * CELLS_PER_GROUP)  // 16; 98000 = 6125 * 16

struct __align__(16) CellParam {
    int   o00, o01, o10, o11;   // corner byte offsets (channel 0); o00 low bits = sel
    float a00, a01, a10, a11;   // bilinear weights * validity
};

__device__ CellParam g_cp[NTASKS];

__global__ __launch_bounds__(256) void prep_kernel(const float* __restrict__ boxes)
{
    const int id = blockIdx.x * 256 + threadIdx.x;
    if (id >= NTASKS) return;

    const int box  = id / NCELLS;
    const int cell = id - box * NCELLS;
    const int b    = (box >= NBOXES) ? 1 : 0;

    const float y1 = __ldg(boxes + box * 4 + 0);
    const float x1 = __ldg(boxes + box * 4 + 1);
    const float y2 = __ldg(boxes + box * 4 + 2);
    const float x2 = __ldg(boxes + box * 4 + 3);
    const float h  = y2 - y1;
    const float w  = x2 - x1;

    float lvlf = ceilf(5.0f + logf(h * w) / 0.6931471805599453f);
    lvlf = fminf(fmaxf(lvlf, 3.0f), 5.0f);
    const int level = (int)lvlf;

    const int HW = (level == 3) ? 128 : (level == 4) ? 64 : 32;

    const float Hm1 = (float)(HW - 1);
    const int   iy  = cell / POOL_W;
    const int   ix  = cell - iy * POOL_W;
    // exact reference rounding order for all discrete decisions
    const float stepy = __fdiv_rn(__fmul_rn(h, Hm1), 6.0f);
    const float stepx = __fdiv_rn(__fmul_rn(w, Hm1), 6.0f);
    const float ys = __fadd_rn(__fmul_rn(y1, Hm1), __fmul_rn((float)iy, stepy));
    const float xs = __fadd_rn(__fmul_rn(x1, Hm1), __fmul_rn((float)ix, stepx));

    const bool  valid = (ys >= 0.0f) & (ys <= Hm1) & (xs >= 0.0f) & (xs <= Hm1);
    const float vm = valid ? 1.0f : 0.0f;

    const float y0f = floorf(ys);
    const float x0f = floorf(xs);
    const float wy  = ys - y0f;
    const float wx  = xs - x0f;
    const float owy = 1.0f - wy;
    const float owx = 1.0f - wx;

    const int y0i = (int)fminf(fmaxf(y0f, 0.0f), Hm1);
    const int y1i = (int)fminf(fmaxf(y0f + 1.0f, 0.0f), Hm1);
    const int x0i = (int)fminf(fmaxf(x0f, 0.0f), Hm1);
    const int x1i = (int)fminf(fmaxf(x0f + 1.0f, 0.0f), Hm1);

    const int rowbytes = HW * NCH * 4;
    const int sel = (level - 3) * 2 + b;        // 0..5, in low bits (offsets % 1024 == 0)

    CellParam p;
    p.o00 = (y0i * rowbytes + x0i * (NCH * 4)) | sel;
    p.o01 = y0i * rowbytes + x1i * (NCH * 4);
    p.o10 = y1i * rowbytes + x0i * (NCH * 4);
    p.o11 = y1i * rowbytes + x1i * (NCH * 4);
    p.a00 = owx * owy * vm;
    p.a01 = wx  * owy * vm;
    p.a10 = owx * wy  * vm;
    p.a11 = wx  * wy  * vm;
    g_cp[id] = p;
}

__global__ __launch_bounds__(256) void gather_kernel(
    const float* __restrict__ p3,
    const float* __restrict__ p4,
    const float* __restrict__ p5,
    float* __restrict__ out)
{
    const int local = threadIdx.x >> 6;          // group 0..3
    const int lane  = threadIdx.x & 63;          // float4 channel group
    const int base  = blockIdx.x * TASKS_PER_BLOCK + local * CELLS_PER_GROUP;

    #pragma unroll 2
    for (int i = 0; i < CELLS_PER_GROUP; i++) {
        const int pt = base + i;

        int4   oo = __ldg((const int4*)&g_cp[pt]);
        float4 aa = __ldg((const float4*)&g_cp[pt] + 1);

        const int sel = oo.x & 7;
        oo.x &= ~1023;

        const int lvl = sel >> 1;
        const int b   = sel & 1;
        const float* fb;
        int HW;
        if (lvl == 0)      { fb = p3; HW = 128; }
        else if (lvl == 1) { fb = p4; HW = 64;  }
        else               { fb = p5; HW = 32;  }

        const char* basep = (const char*)(fb + (size_t)b * HW * HW * NCH) + lane * 16;

        const float4 v00 = __ldg((const float4*)(basep + oo.x));
        const float4 v01 = __ldg((const float4*)(basep + oo.y));
        const float4 v10 = __ldg((const float4*)(basep + oo.z));
        const float4 v11 = __ldg((const float4*)(basep + oo.w));

        float4 o;
        o.x = v00.x * aa.x + v01.x * aa.y + v10.x * aa.z + v11.x * aa.w;
        o.y = v00.y * aa.x + v01.y * aa.y + v10.y * aa.z + v11.y * aa.w;
        o.z = v00.z * aa.x + v01.z * aa.y + v10.z * aa.z + v11.z * aa.w;
        o.w = v00.w * aa.x + v01.w * aa.y + v10.w * aa.z + v11.w * aa.w;

        __stcs((float4*)out + (size_t)pt * 64 + lane, o);
    }
}

extern "C" void kernel_launch(void* const* d_in, const int* in_sizes, int n_in,
                              void* d_out, int out_size) {
    const float* boxes = (const float*)d_in[0];
    const float* p3    = (const float*)d_in[2];
    const float* p4    = (const float*)d_in[3];
    const float* p5    = (const float*)d_in[4];
    float* out = (float*)d_out;

    prep_kernel<<<(NTASKS + 255) / 256, 256>>>(boxes);
    gather_kernel<<<NTASKS / TASKS_PER_BLOCK, 256>>>(p3, p4, p5, out);
}